// round 7
// baseline (speedup 1.0000x reference)
#include <cuda_runtime.h>
#include <cuda_bf16.h>
#include <stdint.h>
#include <math.h>

// Problem constants
#define BATCH 2
#define SEQ   2048
#define CDIM  768
#define NHEAD 12
#define HDIM  64
#define BHTOT (BATCH*NHEAD)          // 24
#define MROWS (BATCH*SEQ)            // 4096
#define QKVN  (3*CDIM)               // 2304

// ---------------- scratch (device globals; no allocation allowed) -------------
__device__ float g_qkv[(size_t)MROWS * QKVN];          // 4096 x 2304
__device__ float g_q[(size_t)BHTOT * SEQ * HDIM];      // [bh][n][d] (tf32-rounded)
__device__ float g_k[(size_t)BHTOT * SEQ * HDIM];      // [bh][n][d]
__device__ float g_v[(size_t)BHTOT * SEQ * HDIM];      // [bh][d][n]  (TRANSPOSED)
__device__ float g_attn[(size_t)MROWS * CDIM];         // attention out, [b*n][c]

// ---------------- helpers ------------------------------------------------------
__device__ __forceinline__ uint32_t tf32r(float f) {
    uint32_t u;
    asm("cvt.rna.tf32.f32 %0, %1;" : "=r"(u) : "f"(f));
    return u;
}
__device__ __forceinline__ float tf32f(float f) { return __uint_as_float(tf32r(f)); }

__device__ __forceinline__ float ex2f(float x) {
    float y;
    asm("ex2.approx.f32 %0, %1;" : "=f"(y) : "f"(x));
    return y;
}

// mma.m16n8k8 tf32: D += A*B, A row-major 16x8, B col-major 8x8, fp32 accum
__device__ __forceinline__ void mma8(float* c, const uint32_t* a, uint32_t b0, uint32_t b1) {
    asm volatile(
        "mma.sync.aligned.m16n8k8.row.col.f32.tf32.tf32.f32 "
        "{%0,%1,%2,%3}, {%4,%5,%6,%7}, {%8,%9}, {%0,%1,%2,%3};\n"
        : "+f"(c[0]), "+f"(c[1]), "+f"(c[2]), "+f"(c[3])
        : "r"(a[0]), "r"(a[1]), "r"(a[2]), "r"(a[3]), "r"(b0), "r"(b1));
}

// ldmatrix x4 (b16 granularity; pure data movement, fine for 32-bit elements)
__device__ __forceinline__ void ldsm4(uint32_t* r, uint32_t smem_addr) {
    asm volatile("ldmatrix.sync.aligned.m8n8.x4.shared.b16 {%0,%1,%2,%3}, [%4];\n"
        : "=r"(r[0]), "=r"(r[1]), "=r"(r[2]), "=r"(r[3]) : "r"(smem_addr));
}

__device__ __forceinline__ void cp_async16(void* dst_smem, const void* src_gmem) {
    uint32_t d = (uint32_t)__cvta_generic_to_shared(dst_smem);
    asm volatile("cp.async.cg.shared.global [%0], [%1], 16;\n" :: "r"(d), "l"(src_gmem));
}
__device__ __forceinline__ void cp_commit() { asm volatile("cp.async.commit_group;\n"); }
__device__ __forceinline__ void cp_wait1()  { asm volatile("cp.async.wait_group 1;\n"); }

// Permute a 16x8 mma accumulator tile (P, register layout) into the A-fragment
// layout of the next m16n8k8 mma, via intra-warp shuffles.
__device__ __forceinline__ void pfrag(const float* c, int srcA, int srcB, bool odd,
                                      uint32_t* a) {
    float v00 = __shfl_sync(0xffffffffu, c[0], srcA);
    float v01 = __shfl_sync(0xffffffffu, c[1], srcA);
    float v10 = __shfl_sync(0xffffffffu, c[2], srcA);
    float v11 = __shfl_sync(0xffffffffu, c[3], srcA);
    float w00 = __shfl_sync(0xffffffffu, c[0], srcB);
    float w01 = __shfl_sync(0xffffffffu, c[1], srcB);
    float w10 = __shfl_sync(0xffffffffu, c[2], srcB);
    float w11 = __shfl_sync(0xffffffffu, c[3], srcB);
    a[0] = __float_as_uint(odd ? v01 : v00);
    a[1] = __float_as_uint(odd ? v11 : v10);
    a[2] = __float_as_uint(odd ? w01 : w00);
    a[3] = __float_as_uint(odd ? w11 : w10);
}

// ---------------- TF32 tensor-core SGEMM + bias --------------------------------
#define AS_STRIDE 20
#define BS_STRIDE 136
__global__ __launch_bounds__(256) void sgemm_tf32(
    int M, int N, int K,
    const float* __restrict__ A, const float* __restrict__ B,
    const float* __restrict__ bias, float* __restrict__ C)
{
    __shared__ uint32_t As[128 * AS_STRIDE];  // [row][k] tf32 bits
    __shared__ uint32_t Bs[16 * BS_STRIDE];   // [k][n]   tf32 bits

    const int tid  = threadIdx.x;
    const int warp = tid >> 5;
    const int lane = tid & 31;
    const int g = lane >> 2, t = lane & 3;
    const int warp_m = warp >> 2;     // 0..1
    const int warp_n = warp & 3;      // 0..3
    const int brow = blockIdx.y, bcol = blockIdx.x;

    float acc[4][4][4];
    #pragma unroll
    for (int mt = 0; mt < 4; mt++)
        #pragma unroll
        for (int nt = 0; nt < 4; nt++)
            #pragma unroll
            for (int j = 0; j < 4; j++) acc[mt][nt][j] = 0.f;

    const int af0 = tid, af1 = tid + 256;
    const int bf0 = tid, bf1 = tid + 256;

    float4 pa[2], pb[2];
    {
        const int r0 = af0 >> 2, c0 = (af0 & 3) << 2;
        const int r1 = af1 >> 2, c1 = (af1 & 3) << 2;
        pa[0] = *reinterpret_cast<const float4*>(A + (size_t)(brow * 128 + r0) * K + c0);
        pa[1] = *reinterpret_cast<const float4*>(A + (size_t)(brow * 128 + r1) * K + c1);
        const int kr0 = bf0 >> 5, n0 = (bf0 & 31) << 2;
        const int kr1 = bf1 >> 5, n1 = (bf1 & 31) << 2;
        pb[0] = *reinterpret_cast<const float4*>(B + (size_t)kr0 * N + bcol * 128 + n0);
        pb[1] = *reinterpret_cast<const float4*>(B + (size_t)kr1 * N + bcol * 128 + n1);
    }

    for (int k0 = 0; k0 < K; k0 += 16) {
        {
            const int r0 = af0 >> 2, c0 = (af0 & 3) << 2;
            const int r1 = af1 >> 2, c1 = (af1 & 3) << 2;
            uint4 u0 = { tf32r(pa[0].x), tf32r(pa[0].y), tf32r(pa[0].z), tf32r(pa[0].w) };
            uint4 u1 = { tf32r(pa[1].x), tf32r(pa[1].y), tf32r(pa[1].z), tf32r(pa[1].w) };
            *reinterpret_cast<uint4*>(&As[r0 * AS_STRIDE + c0]) = u0;
            *reinterpret_cast<uint4*>(&As[r1 * AS_STRIDE + c1]) = u1;
            const int kr0 = bf0 >> 5, n0 = (bf0 & 31) << 2;
            const int kr1 = bf1 >> 5, n1 = (bf1 & 31) << 2;
            uint4 v0 = { tf32r(pb[0].x), tf32r(pb[0].y), tf32r(pb[0].z), tf32r(pb[0].w) };
            uint4 v1 = { tf32r(pb[1].x), tf32r(pb[1].y), tf32r(pb[1].z), tf32r(pb[1].w) };
            *reinterpret_cast<uint4*>(&Bs[kr0 * BS_STRIDE + n0]) = v0;
            *reinterpret_cast<uint4*>(&Bs[kr1 * BS_STRIDE + n1]) = v1;
        }
        __syncthreads();

        if (k0 + 16 < K) {
            const int r0 = af0 >> 2, c0 = (af0 & 3) << 2;
            const int r1 = af1 >> 2, c1 = (af1 & 3) << 2;
            pa[0] = *reinterpret_cast<const float4*>(A + (size_t)(brow * 128 + r0) * K + k0 + 16 + c0);
            pa[1] = *reinterpret_cast<const float4*>(A + (size_t)(brow * 128 + r1) * K + k0 + 16 + c1);
            const int kr0 = bf0 >> 5, n0 = (bf0 & 31) << 2;
            const int kr1 = bf1 >> 5, n1 = (bf1 & 31) << 2;
            pb[0] = *reinterpret_cast<const float4*>(B + (size_t)(k0 + 16 + kr0) * N + bcol * 128 + n0);
            pb[1] = *reinterpret_cast<const float4*>(B + (size_t)(k0 + 16 + kr1) * N + bcol * 128 + n1);
        }

        #pragma unroll
        for (int s = 0; s < 2; s++) {
            const int ko = s * 8;
            uint32_t a[4][4], bf[4][2];
            #pragma unroll
            for (int mt = 0; mt < 4; mt++) {
                const int r = warp_m * 64 + mt * 16 + g;
                a[mt][0] = As[r * AS_STRIDE + ko + t];
                a[mt][1] = As[(r + 8) * AS_STRIDE + ko + t];
                a[mt][2] = As[r * AS_STRIDE + ko + t + 4];
                a[mt][3] = As[(r + 8) * AS_STRIDE + ko + t + 4];
            }
            #pragma unroll
            for (int nt = 0; nt < 4; nt++) {
                const int c = warp_n * 32 + nt * 8 + g;
                bf[nt][0] = Bs[(ko + t) * BS_STRIDE + c];
                bf[nt][1] = Bs[(ko + t + 4) * BS_STRIDE + c];
            }
            #pragma unroll
            for (int mt = 0; mt < 4; mt++)
                #pragma unroll
                for (int nt = 0; nt < 4; nt++)
                    mma8(acc[mt][nt], a[mt], bf[nt][0], bf[nt][1]);
        }
        __syncthreads();
    }

    #pragma unroll
    for (int mt = 0; mt < 4; mt++) {
        const int r0 = brow * 128 + warp_m * 64 + mt * 16 + g;
        #pragma unroll
        for (int nt = 0; nt < 4; nt++) {
            const int c = bcol * 128 + warp_n * 32 + nt * 8 + 2 * t;
            float b0 = bias[c], b1 = bias[c + 1];
            float2 v0 = { acc[mt][nt][0] + b0, acc[mt][nt][1] + b1 };
            float2 v1 = { acc[mt][nt][2] + b0, acc[mt][nt][3] + b1 };
            *reinterpret_cast<float2*>(C + (size_t)r0 * N + c) = v0;
            *reinterpret_cast<float2*>(C + (size_t)(r0 + 8) * N + c) = v1;
        }
    }
}

// --------- QKV post: RMSNorm(q,k) + RoPE(q,k) + scale(q), scatter, tf32-round --
// V is written TRANSPOSED: g_v[bh][d][n] so flash can ldmatrix its B-fragments.
__global__ __launch_bounds__(256) void qkv_post(
    const float* __restrict__ qkv,
    const float* __restrict__ cosb, const float* __restrict__ sinb,
    const float* __restrict__ qw,   const float* __restrict__ kw,
    float* __restrict__ Q, float* __restrict__ K, float* __restrict__ V)
{
    int warp = (blockIdx.x * blockDim.x + threadIdx.x) >> 5;
    int lane = threadIdx.x & 31;
    const int NW = BATCH * SEQ * NHEAD;
    if (warp >= NW) return;
    int h = warp % NHEAD;
    int n = (warp / NHEAD) % SEQ;
    int b = warp / (NHEAD * SEQ);

    const float* row = qkv + (size_t)(b * SEQ + n) * QKVN;
    float q0 = row[h * 64 + lane],            q1 = row[h * 64 + lane + 32];
    float k0 = row[CDIM + h * 64 + lane],     k1 = row[CDIM + h * 64 + lane + 32];
    float v0 = row[2 * CDIM + h * 64 + lane], v1 = row[2 * CDIM + h * 64 + lane + 32];

    float sq = q0 * q0 + q1 * q1;
    float sk = k0 * k0 + k1 * k1;
    #pragma unroll
    for (int o = 16; o > 0; o >>= 1) {
        sq += __shfl_xor_sync(0xffffffffu, sq, o);
        sk += __shfl_xor_sync(0xffffffffu, sk, o);
    }
    float rq = rsqrtf(sq * (1.0f / 64.0f) + 1e-6f);
    float rk = rsqrtf(sk * (1.0f / 64.0f) + 1e-6f);
    q0 *= rq * qw[lane]; q1 *= rq * qw[lane + 32];
    k0 *= rk * kw[lane]; k1 *= rk * kw[lane + 32];

    float c0 = cosb[n * 64 + lane], c1 = cosb[n * 64 + lane + 32];
    float s0 = sinb[n * 64 + lane], s1 = sinb[n * 64 + lane + 32];
    float qr0 = q0 * c0 - q1 * s0;
    float qr1 = q1 * c1 + q0 * s1;
    float kr0 = k0 * c0 - k1 * s0;
    float kr1 = k1 * c1 + k0 * s1;

    const float scale = 0.125f * 1.4426950408889634f;  // 1/sqrt(64) * log2(e)
    int bh = b * NHEAD + h;
    float* qo = Q + ((size_t)bh * SEQ + n) * 64;
    float* ko = K + ((size_t)bh * SEQ + n) * 64;
    qo[lane] = tf32f(qr0 * scale); qo[lane + 32] = tf32f(qr1 * scale);
    ko[lane] = tf32f(kr0);         ko[lane + 32] = tf32f(kr1);
    // transposed V: [bh][d][n]
    V[((size_t)bh * 64 + lane)      * SEQ + n] = tf32f(v0);
    V[((size_t)bh * 64 + lane + 32) * SEQ + n] = tf32f(v1);
}

// ---------------- TF32 flash attention (ldmatrix operand loads) -----------------
// CTA: 128 threads (4 warps), Bq=128, Bk=64, d=64. Warp w owns rows [32w,32w+32).
// Q/K/V fragments loaded via ldmatrix.x4; P stays in registers (shfl permute).
// V is d-major in gmem AND smem so its B-frag is ldmatrix-compatible.
#define BQ 128
#define QS_STR 68
#define KS_STR 68
#define VT_STR 68
#define QS_OFF 0
#define KS_OFF (BQ*QS_STR)                  // 8704
#define VS_OFF (KS_OFF + 2*64*KS_STR)       // 17408
#define FLASH_SMEM_WORDS (VS_OFF + 2*64*VT_STR) // 26112
#define FLASH_SMEM_BYTES (FLASH_SMEM_WORDS * 4) // 104448

__global__ __launch_bounds__(128, 2) void flash_tf32(
    const float* __restrict__ Q, const float* __restrict__ K,
    const float* __restrict__ V, float* __restrict__ Out)
{
    extern __shared__ uint32_t sm4[];
    const uint32_t smemu = (uint32_t)__cvta_generic_to_shared(sm4);

    const int bh = blockIdx.y;
    const int q0 = blockIdx.x * BQ;
    const int tid  = threadIdx.x;
    const int warp = tid >> 5;
    const int lane = tid & 31;
    const int g = lane >> 2, t = lane & 3;
    const int base = warp * 32;
    const int srcA = (lane & 28) | ((lane & 3) >> 1);   // holder of P[.][t]
    const int srcB = srcA + 2;                          // holder of P[.][t+4]
    const bool odd = (t & 1);

    // ldmatrix per-lane row offsets (words)
    const int sel = lane >> 3, rw = lane & 7;
    // A-tiles (Q): r0=[rows 0-7,k0-3] r1=[rows 8-15,k0-3] r2=[rows0-7,k4-7] r3=[rows8-15,k4-7]
    const int qoff = ((sel & 1) * 8 + rw) * QS_STR + (sel >> 1) * 4;
    // B-tiles (K/V): r0=[n0-7,k0-3] r1=[n0-7,k4-7] r2=[n8-15,k0-3] r3=[n8-15,k4-7]
    const int koff = ((sel >> 1) * 8 + rw) * KS_STR + (sel & 1) * 4;
    const int voff = ((sel >> 1) * 8 + rw) * VT_STR + (sel & 1) * 4;

    const uint32_t Qa = smemu + 4u * (QS_OFF + base * QS_STR + qoff);

    const float* Qg = Q + ((size_t)bh * SEQ + q0) * 64;
    const float* Kg = K + (size_t)bh * SEQ * 64;
    const float* Vg = V + (size_t)bh * 64 * SEQ;   // [d][n]

    // prologue: stage Q and KV tile 0 (group 0), KV tile 1 (group 1)
    #pragma unroll
    for (int j = 0; j < 16; j++) {
        int f = j * 128 + tid;              // 0..2047
        int r = f >> 4, d4 = (f & 15) << 2;
        cp_async16(&sm4[QS_OFF + r * QS_STR + d4], Qg + f * 4);
    }
    #pragma unroll
    for (int bufp = 0; bufp < 2; bufp++) {
        uint32_t* Kb = sm4 + KS_OFF + bufp * 64 * KS_STR;
        uint32_t* Vb = sm4 + VS_OFF + bufp * 64 * VT_STR;
        #pragma unroll
        for (int j = 0; j < 8; j++) {
            int f = j * 128 + tid;          // 0..1023
            int r = f >> 4, d4 = (f & 15) << 2;
            cp_async16(&Kb[r * KS_STR + d4], Kg + (size_t)bufp * 64 * 64 + f * 4);
            // V tile: rows are d, cols are n in [bufp*64, bufp*64+64)
            cp_async16(&Vb[r * VT_STR + d4], Vg + (size_t)r * SEQ + bufp * 64 + d4);
        }
        cp_commit();
    }

    float o[2][8][4];
    float mstate[2][2], lstate[2][2];
    #pragma unroll
    for (int mt = 0; mt < 2; mt++) {
        mstate[mt][0] = -INFINITY; mstate[mt][1] = -INFINITY;
        lstate[mt][0] = 0.f;       lstate[mt][1] = 0.f;
        #pragma unroll
        for (int nt = 0; nt < 8; nt++)
            #pragma unroll
            for (int j = 0; j < 4; j++) o[mt][nt][j] = 0.f;
    }

    const int NIT = SEQ / 64;  // 32
    for (int it = 0; it < NIT; it++) {
        const int buf = it & 1;
        const uint32_t Ka = smemu + 4u * (KS_OFF + buf * 64 * KS_STR + koff);
        const uint32_t Va = smemu + 4u * (VS_OFF + buf * 64 * VT_STR + voff);

        cp_wait1();
        __syncthreads();

        // ---- S = Q K^T (log2-scaled) ----
        float sacc[2][8][4];
        #pragma unroll
        for (int mt = 0; mt < 2; mt++)
            #pragma unroll
            for (int nt = 0; nt < 8; nt++)
                #pragma unroll
                for (int j = 0; j < 4; j++) sacc[mt][nt][j] = 0.f;

        #pragma unroll
        for (int ks = 0; ks < 8; ks++) {
            uint32_t a0[4], a1[4];
            ldsm4(a0, Qa + 4u * (ks * 8));
            ldsm4(a1, Qa + 4u * (16 * QS_STR + ks * 8));
            #pragma unroll
            for (int p = 0; p < 4; p++) {
                uint32_t b[4];
                ldsm4(b, Ka + 4u * (p * 16 * KS_STR + ks * 8));
                mma8(sacc[0][2 * p],     a0, b[0], b[1]);
                mma8(sacc[0][2 * p + 1], a0, b[2], b[3]);
                mma8(sacc[1][2 * p],     a1, b[0], b[1]);
                mma8(sacc[1][2 * p + 1], a1, b[2], b[3]);
            }
        }

        // ---- online softmax (exp2 domain); p stays in registers (tf32-rounded) ----
        #pragma unroll
        for (int mt = 0; mt < 2; mt++) {
            #pragma unroll
            for (int h = 0; h < 2; h++) {
                float mx = -INFINITY;
                #pragma unroll
                for (int nt = 0; nt < 8; nt++)
                    mx = fmaxf(mx, fmaxf(sacc[mt][nt][2 * h], sacc[mt][nt][2 * h + 1]));
                mx = fmaxf(mx, __shfl_xor_sync(0xffffffffu, mx, 1));
                mx = fmaxf(mx, __shfl_xor_sync(0xffffffffu, mx, 2));
                float mn = fmaxf(mstate[mt][h], mx);
                float alpha = ex2f(mstate[mt][h] - mn);
                float sum = 0.f;
                #pragma unroll
                for (int nt = 0; nt < 8; nt++) {
                    float p0 = tf32f(ex2f(sacc[mt][nt][2 * h] - mn));
                    float p1 = tf32f(ex2f(sacc[mt][nt][2 * h + 1] - mn));
                    sacc[mt][nt][2 * h]     = p0;
                    sacc[mt][nt][2 * h + 1] = p1;
                    sum += p0 + p1;
                }
                sum += __shfl_xor_sync(0xffffffffu, sum, 1);
                sum += __shfl_xor_sync(0xffffffffu, sum, 2);
                lstate[mt][h] = lstate[mt][h] * alpha + sum;
                mstate[mt][h] = mn;
                #pragma unroll
                for (int nt = 0; nt < 8; nt++) {
                    o[mt][nt][2 * h]     *= alpha;
                    o[mt][nt][2 * h + 1] *= alpha;
                }
            }
        }

        // ---- O += P V  (P fragments via shfl; V fragments via ldmatrix) ----
        #pragma unroll
        for (int ks = 0; ks < 8; ks++) {
            uint32_t a0[4], a1[4];
            pfrag(sacc[0][ks], srcA, srcB, odd, a0);
            pfrag(sacc[1][ks], srcA, srcB, odd, a1);
            #pragma unroll
            for (int p = 0; p < 4; p++) {
                uint32_t b[4];
                ldsm4(b, Va + 4u * (p * 16 * VT_STR + ks * 8));
                mma8(o[0][2 * p],     a0, b[0], b[1]);
                mma8(o[0][2 * p + 1], a0, b[2], b[3]);
                mma8(o[1][2 * p],     a1, b[0], b[1]);
                mma8(o[1][2 * p + 1], a1, b[2], b[3]);
            }
        }

        __syncthreads();  // all warps done with this K/V buffer

        // stage KV tile it+2 into this buffer
        if (it + 2 < NIT) {
            uint32_t* Kn = sm4 + KS_OFF + buf * 64 * KS_STR;
            uint32_t* Vn = sm4 + VS_OFF + buf * 64 * VT_STR;
            const float* Kp = Kg + (size_t)(it + 2) * 64 * 64;
            const int ncol = (it + 2) * 64;
            #pragma unroll
            for (int j = 0; j < 8; j++) {
                int f = j * 128 + tid;
                int r = f >> 4, d4 = (f & 15) << 2;
                cp_async16(&Kn[r * KS_STR + d4], Kp + f * 4);
                cp_async16(&Vn[r * VT_STR + d4], Vg + (size_t)r * SEQ + ncol + d4);
            }
        }
        cp_commit();
    }

    // ---- epilogue: normalize and write to [b, n, h*64+d] ----
    const int b = bh / NHEAD, hh = bh % NHEAD;
    #pragma unroll
    for (int mt = 0; mt < 2; mt++) {
        #pragma unroll
        for (int h = 0; h < 2; h++) {
            const float inv = 1.0f / lstate[mt][h];
            const int n = q0 + base + mt * 16 + g + 8 * h;
            float* orow = Out + ((size_t)(b * SEQ + n)) * CDIM + hh * 64;
            #pragma unroll
            for (int nt = 0; nt < 8; nt++) {
                float2 v = { o[mt][nt][2 * h] * inv, o[mt][nt][2 * h + 1] * inv };
                *reinterpret_cast<float2*>(orow + nt * 8 + 2 * t) = v;
            }
        }
    }
}

// ------------------------------- launcher -------------------------------------
extern "C" void kernel_launch(void* const* d_in, const int* in_sizes, int n_in,
                              void* d_out, int out_size)
{
    const float* x        = (const float*)d_in[0];
    const float* rope_cos = (const float*)d_in[1];
    const float* rope_sin = (const float*)d_in[2];
    const float* qkv_k    = (const float*)d_in[3];
    const float* qkv_b    = (const float*)d_in[4];
    const float* proj_k   = (const float*)d_in[5];
    const float* proj_b   = (const float*)d_in[6];
    const float* qw       = (const float*)d_in[7];
    const float* kw       = (const float*)d_in[8];
    float* out = (float*)d_out;

    float *p_qkv, *p_q, *p_k, *p_v, *p_attn;
    cudaGetSymbolAddress((void**)&p_qkv,  g_qkv);
    cudaGetSymbolAddress((void**)&p_q,    g_q);
    cudaGetSymbolAddress((void**)&p_k,    g_k);
    cudaGetSymbolAddress((void**)&p_v,    g_v);
    cudaGetSymbolAddress((void**)&p_attn, g_attn);

    // 1) QKV GEMM: [4096,768] x [768,2304]
    {
        dim3 grid(QKVN / 128, MROWS / 128);
        sgemm_tf32<<<grid, 256>>>(MROWS, QKVN, CDIM, x, qkv_k, qkv_b, p_qkv);
    }

    // 2) RMSNorm + RoPE + scatter (V transposed)
    {
        int warps = BATCH * SEQ * NHEAD;
        int blocks = (warps * 32 + 255) / 256;
        qkv_post<<<blocks, 256>>>(p_qkv, rope_cos, rope_sin, qw, kw, p_q, p_k, p_v);
    }

    // 3) flash attention (tf32 mma + ldmatrix, 2 CTAs/SM)
    {
        cudaFuncSetAttribute(flash_tf32, cudaFuncAttributeMaxDynamicSharedMemorySize,
                             FLASH_SMEM_BYTES);
        dim3 grid(SEQ / BQ, BHTOT);
        flash_tf32<<<grid, 128, FLASH_SMEM_BYTES>>>(p_q, p_k, p_v, p_attn);
    }

    // 4) projection GEMM: [4096,768] x [768,768] -> d_out
    {
        dim3 grid(CDIM / 128, MROWS / 128);
        sgemm_tf32<<<grid, 256>>>(MROWS, CDIM, CDIM, p_attn, proj_k, proj_b, out);
    }
}

// round 9
// speedup vs baseline: 1.0951x; 1.0951x over previous
#include <cuda_runtime.h>
#include <cuda_bf16.h>
#include <stdint.h>
#include <math.h>

// Problem constants
#define BATCH 2
#define SEQ   2048
#define CDIM  768
#define NHEAD 12
#define HDIM  64
#define BHTOT (BATCH*NHEAD)          // 24
#define MROWS (BATCH*SEQ)            // 4096
#define QKVN  (3*CDIM)               // 2304

// ---------------- scratch (device globals; no allocation allowed) -------------
__device__ float g_qkv[(size_t)MROWS * QKVN];          // 4096 x 2304
__device__ float g_q[(size_t)BHTOT * SEQ * HDIM];
__device__ float g_k[(size_t)BHTOT * SEQ * HDIM];
__device__ float g_v[(size_t)BHTOT * SEQ * HDIM];
__device__ float g_attn[(size_t)MROWS * CDIM];         // tf32-rounded by flash epilogue
__device__ float g_xr[(size_t)MROWS * CDIM];           // tf32-rounded x
__device__ float g_wqr[(size_t)CDIM * QKVN];           // tf32-rounded qkv_kernel
__device__ float g_wpr[(size_t)CDIM * CDIM];           // tf32-rounded proj_kernel

// ---------------- helpers ------------------------------------------------------
__device__ __forceinline__ uint32_t tf32r(float f) {
    uint32_t u; asm("cvt.rna.tf32.f32 %0, %1;" : "=r"(u) : "f"(f)); return u;
}
__device__ __forceinline__ float tf32f(float f) { return __uint_as_float(tf32r(f)); }
__device__ __forceinline__ float ex2f(float x) {
    float y; asm("ex2.approx.f32 %0, %1;" : "=f"(y) : "f"(x)); return y;
}
__device__ __forceinline__ void mma8(float* c, const uint32_t* a, uint32_t b0, uint32_t b1) {
    asm volatile(
        "mma.sync.aligned.m16n8k8.row.col.f32.tf32.tf32.f32 "
        "{%0,%1,%2,%3}, {%4,%5,%6,%7}, {%8,%9}, {%0,%1,%2,%3};\n"
        : "+f"(c[0]), "+f"(c[1]), "+f"(c[2]), "+f"(c[3])
        : "r"(a[0]), "r"(a[1]), "r"(a[2]), "r"(a[3]), "r"(b0), "r"(b1));
}
__device__ __forceinline__ void cp_async16(void* dst_smem, const void* src_gmem) {
    uint32_t d = (uint32_t)__cvta_generic_to_shared(dst_smem);
    asm volatile("cp.async.cg.shared.global [%0], [%1], 16;\n" :: "r"(d), "l"(src_gmem));
}
__device__ __forceinline__ void cp_commit() { asm volatile("cp.async.commit_group;\n"); }
__device__ __forceinline__ void cp_wait1()  { asm volatile("cp.async.wait_group 1;\n"); }

__device__ __forceinline__ void pfrag(const float* c, int srcA, int srcB, bool odd,
                                      uint32_t* a) {
    float v00 = __shfl_sync(0xffffffffu, c[0], srcA);
    float v01 = __shfl_sync(0xffffffffu, c[1], srcA);
    float v10 = __shfl_sync(0xffffffffu, c[2], srcA);
    float v11 = __shfl_sync(0xffffffffu, c[3], srcA);
    float w00 = __shfl_sync(0xffffffffu, c[0], srcB);
    float w01 = __shfl_sync(0xffffffffu, c[1], srcB);
    float w10 = __shfl_sync(0xffffffffu, c[2], srcB);
    float w11 = __shfl_sync(0xffffffffu, c[3], srcB);
    a[0] = __float_as_uint(odd ? v01 : v00);
    a[1] = __float_as_uint(odd ? v11 : v10);
    a[2] = __float_as_uint(odd ? w01 : w00);
    a[3] = __float_as_uint(odd ? w11 : w10);
}

// ---------------- prep: round fp32 -> tf32 bits in gmem -------------------------
__global__ __launch_bounds__(256) void round_tf32(
    const float* __restrict__ src, float* __restrict__ dst, int n4)
{
    int i = blockIdx.x * blockDim.x + threadIdx.x;
    if (i >= n4) return;
    float4 v = *reinterpret_cast<const float4*>(src + (size_t)i * 4);
    v.x = tf32f(v.x); v.y = tf32f(v.y); v.z = tf32f(v.z); v.w = tf32f(v.w);
    *reinterpret_cast<float4*>(dst + (size_t)i * 4) = v;
}

// ---------------- TF32 tensor-core SGEMM + bias (v2: BK=32, 3-stage cp.async) ---
// C[M,N] = A[M,K] @ B[K,N] + bias. Inputs pre-rounded to tf32.
// BM=BN=128, BK=32, 256 thr (8 warps 2x4), warp tile 64x32, mma m16n8k8.
#define AS_STR 36
#define BS_STR 136
#define STAGE_WORDS (128*AS_STR + 32*BS_STR)   // 4608 + 4352 = 8960
#define SG_SMEM (3*STAGE_WORDS*4)              // 107520 B

__global__ __launch_bounds__(256) void sgemm_tf32(
    int M, int N, int K,
    const float* __restrict__ A, const float* __restrict__ B,
    const float* __restrict__ bias, float* __restrict__ C)
{
    extern __shared__ uint32_t smw[];

    const int tid  = threadIdx.x;
    const int warp = tid >> 5;
    const int lane = tid & 31;
    const int g = lane >> 2, t = lane & 3;
    const int warp_m = warp >> 2;     // 0..1
    const int warp_n = warp & 3;      // 0..3
    const int brow = blockIdx.y, bcol = blockIdx.x;

    const float* Ablk = A + (size_t)brow * 128 * K;
    const float* Bblk = B + (size_t)bcol * 128;
    const int ktiles = K >> 5;

    float acc[4][4][4];
    #pragma unroll
    for (int mt = 0; mt < 4; mt++)
        #pragma unroll
        for (int nt = 0; nt < 4; nt++)
            #pragma unroll
            for (int j = 0; j < 4; j++) acc[mt][nt][j] = 0.f;

    // stage kt into slot s
    auto stage = [&](int kt, int s) {
        uint32_t* As = smw + s * STAGE_WORDS;
        uint32_t* Bs = As + 128 * AS_STR;
        #pragma unroll
        for (int j = 0; j < 4; j++) {
            int f = j * 256 + tid;                 // 0..1023
            int r = f >> 3, c4 = (f & 7) << 2;     // A: 128 rows x 32 cols
            cp_async16(&As[r * AS_STR + c4], Ablk + (size_t)r * K + kt * 32 + c4);
        }
        #pragma unroll
        for (int j = 0; j < 4; j++) {
            int f = j * 256 + tid;
            int kr = f >> 5, n4 = (f & 31) << 2;   // B: 32 rows x 128 cols
            cp_async16(&Bs[kr * BS_STR + n4], Bblk + (size_t)(kt * 32 + kr) * N + n4);
        }
    };

    stage(0, 0); cp_commit();
    stage(1, 1); cp_commit();

    for (int kt = 0; kt < ktiles; kt++) {
        cp_wait1();
        __syncthreads();
        if (kt + 2 < ktiles) stage(kt + 2, (kt + 2) % 3);
        cp_commit();   // empty group when no prefetch — keeps wait_group(1) sound

        const uint32_t* As = smw + (kt % 3) * STAGE_WORDS;
        const uint32_t* Bs = As + 128 * AS_STR;

        #pragma unroll
        for (int s = 0; s < 4; s++) {
            const int ko = s * 8;
            uint32_t a[4][4], bf[4][2];
            #pragma unroll
            for (int mt = 0; mt < 4; mt++) {
                const int r = warp_m * 64 + mt * 16 + g;
                a[mt][0] = As[r * AS_STR + ko + t];
                a[mt][1] = As[(r + 8) * AS_STR + ko + t];
                a[mt][2] = As[r * AS_STR + ko + t + 4];
                a[mt][3] = As[(r + 8) * AS_STR + ko + t + 4];
            }
            #pragma unroll
            for (int nt = 0; nt < 4; nt++) {
                const int c = warp_n * 32 + nt * 8 + g;
                bf[nt][0] = Bs[(ko + t) * BS_STR + c];
                bf[nt][1] = Bs[(ko + t + 4) * BS_STR + c];
            }
            #pragma unroll
            for (int mt = 0; mt < 4; mt++)
                #pragma unroll
                for (int nt = 0; nt < 4; nt++)
                    mma8(acc[mt][nt], a[mt], bf[nt][0], bf[nt][1]);
        }
    }

    // epilogue: bias + store
    #pragma unroll
    for (int mt = 0; mt < 4; mt++) {
        const int r0 = brow * 128 + warp_m * 64 + mt * 16 + g;
        #pragma unroll
        for (int nt = 0; nt < 4; nt++) {
            const int c = bcol * 128 + warp_n * 32 + nt * 8 + 2 * t;
            float b0 = bias[c], b1 = bias[c + 1];
            float2 v0 = { acc[mt][nt][0] + b0, acc[mt][nt][1] + b1 };
            float2 v1 = { acc[mt][nt][2] + b0, acc[mt][nt][3] + b1 };
            *reinterpret_cast<float2*>(C + (size_t)r0 * N + c) = v0;
            *reinterpret_cast<float2*>(C + (size_t)(r0 + 8) * N + c) = v1;
        }
    }
}

// --------- QKV post: RMSNorm(q,k) + RoPE(q,k) + scale(q), scatter, tf32-round --
__global__ __launch_bounds__(256) void qkv_post(
    const float* __restrict__ qkv,
    const float* __restrict__ cosb, const float* __restrict__ sinb,
    const float* __restrict__ qw,   const float* __restrict__ kw,
    float* __restrict__ Q, float* __restrict__ K, float* __restrict__ V)
{
    int warp = (blockIdx.x * blockDim.x + threadIdx.x) >> 5;
    int lane = threadIdx.x & 31;
    const int NW = BATCH * SEQ * NHEAD;
    if (warp >= NW) return;
    int h = warp % NHEAD;
    int n = (warp / NHEAD) % SEQ;
    int b = warp / (NHEAD * SEQ);

    const float* row = qkv + (size_t)(b * SEQ + n) * QKVN;
    float q0 = row[h * 64 + lane],            q1 = row[h * 64 + lane + 32];
    float k0 = row[CDIM + h * 64 + lane],     k1 = row[CDIM + h * 64 + lane + 32];
    float v0 = row[2 * CDIM + h * 64 + lane], v1 = row[2 * CDIM + h * 64 + lane + 32];

    float sq = q0 * q0 + q1 * q1;
    float sk = k0 * k0 + k1 * k1;
    #pragma unroll
    for (int o = 16; o > 0; o >>= 1) {
        sq += __shfl_xor_sync(0xffffffffu, sq, o);
        sk += __shfl_xor_sync(0xffffffffu, sk, o);
    }
    float rq = rsqrtf(sq * (1.0f / 64.0f) + 1e-6f);
    float rk = rsqrtf(sk * (1.0f / 64.0f) + 1e-6f);
    q0 *= rq * qw[lane]; q1 *= rq * qw[lane + 32];
    k0 *= rk * kw[lane]; k1 *= rk * kw[lane + 32];

    float c0 = cosb[n * 64 + lane], c1 = cosb[n * 64 + lane + 32];
    float s0 = sinb[n * 64 + lane], s1 = sinb[n * 64 + lane + 32];
    float qr0 = q0 * c0 - q1 * s0;
    float qr1 = q1 * c1 + q0 * s1;
    float kr0 = k0 * c0 - k1 * s0;
    float kr1 = k1 * c1 + k0 * s1;

    const float scale = 0.125f * 1.4426950408889634f;  // 1/sqrt(64) * log2(e)
    int bh = b * NHEAD + h;
    float* qo = Q + ((size_t)bh * SEQ + n) * 64;
    float* ko = K + ((size_t)bh * SEQ + n) * 64;
    float* vo = V + ((size_t)bh * SEQ + n) * 64;
    qo[lane] = tf32f(qr0 * scale); qo[lane + 32] = tf32f(qr1 * scale);
    ko[lane] = tf32f(kr0);         ko[lane + 32] = tf32f(kr1);
    vo[lane] = tf32f(v0);          vo[lane + 32] = tf32f(v1);
}

// ---------------- TF32 flash attention (R5 config; tf32-rounded output) ---------
#define BQ 128
#define QS_STR 68
#define KS_STR 68
#define VS_STR 72
#define QS_OFF 0
#define KS_OFF (BQ*QS_STR)
#define VS_OFF (KS_OFF + 2*64*KS_STR)
#define FLASH_SMEM_WORDS (VS_OFF + 2*64*VS_STR)
#define FLASH_SMEM_BYTES (FLASH_SMEM_WORDS * 4)   // 106496

__global__ __launch_bounds__(128, 2) void flash_tf32(
    const float* __restrict__ Q, const float* __restrict__ K,
    const float* __restrict__ V, float* __restrict__ Out)
{
    extern __shared__ uint32_t sm4[];
    uint32_t* Qs = sm4 + QS_OFF;

    const int bh = blockIdx.y;
    const int q0 = blockIdx.x * BQ;
    const int tid  = threadIdx.x;
    const int warp = tid >> 5;
    const int lane = tid & 31;
    const int g = lane >> 2, t = lane & 3;
    const int base = warp * 32;
    const int srcA = (lane & 28) | ((lane & 3) >> 1);
    const int srcB = srcA + 2;
    const bool odd = (t & 1);

    const float* Qg = Q + ((size_t)bh * SEQ + q0) * 64;
    const float* Kg = K + (size_t)bh * SEQ * 64;
    const float* Vg = V + (size_t)bh * SEQ * 64;

    #pragma unroll
    for (int j = 0; j < 16; j++) {
        int f = j * 128 + tid;
        int r = f >> 4, d4 = (f & 15) << 2;
        cp_async16(&Qs[r * QS_STR + d4], Qg + f * 4);
    }
    {
        uint32_t* Kb = sm4 + KS_OFF;
        uint32_t* Vb = sm4 + VS_OFF;
        #pragma unroll
        for (int j = 0; j < 8; j++) {
            int f = j * 128 + tid;
            int r = f >> 4, d4 = (f & 15) << 2;
            cp_async16(&Kb[r * KS_STR + d4], Kg + f * 4);
            cp_async16(&Vb[r * VS_STR + d4], Vg + f * 4);
        }
    }
    cp_commit();
    {
        uint32_t* Kb = sm4 + KS_OFF + 64 * KS_STR;
        uint32_t* Vb = sm4 + VS_OFF + 64 * VS_STR;
        #pragma unroll
        for (int j = 0; j < 8; j++) {
            int f = j * 128 + tid;
            int r = f >> 4, d4 = (f & 15) << 2;
            cp_async16(&Kb[r * KS_STR + d4], Kg + 64 * 64 + f * 4);
            cp_async16(&Vb[r * VS_STR + d4], Vg + 64 * 64 + f * 4);
        }
    }
    cp_commit();

    float o[2][8][4];
    float mstate[2][2], lstate[2][2];
    #pragma unroll
    for (int mt = 0; mt < 2; mt++) {
        mstate[mt][0] = -INFINITY; mstate[mt][1] = -INFINITY;
        lstate[mt][0] = 0.f;       lstate[mt][1] = 0.f;
        #pragma unroll
        for (int nt = 0; nt < 8; nt++)
            #pragma unroll
            for (int j = 0; j < 4; j++) o[mt][nt][j] = 0.f;
    }

    const int NIT = SEQ / 64;
    for (int it = 0; it < NIT; it++) {
        const int buf = it & 1;
        uint32_t* Ks = sm4 + KS_OFF + buf * 64 * KS_STR;
        uint32_t* Vs = sm4 + VS_OFF + buf * 64 * VS_STR;

        cp_wait1();
        __syncthreads();

        float sacc[2][8][4];
        #pragma unroll
        for (int mt = 0; mt < 2; mt++)
            #pragma unroll
            for (int nt = 0; nt < 8; nt++)
                #pragma unroll
                for (int j = 0; j < 4; j++) sacc[mt][nt][j] = 0.f;

        #pragma unroll
        for (int ks = 0; ks < 8; ks++) {
            const int ko = ks * 8 + t;
            uint32_t a[2][4];
            #pragma unroll
            for (int mt = 0; mt < 2; mt++) {
                const int r = base + mt * 16 + g;
                a[mt][0] = Qs[r * QS_STR + ko];
                a[mt][1] = Qs[(r + 8) * QS_STR + ko];
                a[mt][2] = Qs[r * QS_STR + ko + 4];
                a[mt][3] = Qs[(r + 8) * QS_STR + ko + 4];
            }
            #pragma unroll
            for (int nt = 0; nt < 8; nt++) {
                const int kr = nt * 8 + g;
                uint32_t b0 = Ks[kr * KS_STR + ko];
                uint32_t b1 = Ks[kr * KS_STR + ko + 4];
                mma8(sacc[0][nt], a[0], b0, b1);
                mma8(sacc[1][nt], a[1], b0, b1);
            }
        }

        #pragma unroll
        for (int mt = 0; mt < 2; mt++) {
            #pragma unroll
            for (int h = 0; h < 2; h++) {
                float mx = -INFINITY;
                #pragma unroll
                for (int nt = 0; nt < 8; nt++)
                    mx = fmaxf(mx, fmaxf(sacc[mt][nt][2 * h], sacc[mt][nt][2 * h + 1]));
                mx = fmaxf(mx, __shfl_xor_sync(0xffffffffu, mx, 1));
                mx = fmaxf(mx, __shfl_xor_sync(0xffffffffu, mx, 2));
                float mn = fmaxf(mstate[mt][h], mx);
                float alpha = ex2f(mstate[mt][h] - mn);
                float sum = 0.f;
                #pragma unroll
                for (int nt = 0; nt < 8; nt++) {
                    float p0 = tf32f(ex2f(sacc[mt][nt][2 * h] - mn));
                    float p1 = tf32f(ex2f(sacc[mt][nt][2 * h + 1] - mn));
                    sacc[mt][nt][2 * h]     = p0;
                    sacc[mt][nt][2 * h + 1] = p1;
                    sum += p0 + p1;
                }
                sum += __shfl_xor_sync(0xffffffffu, sum, 1);
                sum += __shfl_xor_sync(0xffffffffu, sum, 2);
                lstate[mt][h] = lstate[mt][h] * alpha + sum;
                mstate[mt][h] = mn;
                #pragma unroll
                for (int nt = 0; nt < 8; nt++) {
                    o[mt][nt][2 * h]     *= alpha;
                    o[mt][nt][2 * h + 1] *= alpha;
                }
            }
        }

        #pragma unroll
        for (int ks = 0; ks < 8; ks++) {
            uint32_t a0[4], a1[4];
            pfrag(sacc[0][ks], srcA, srcB, odd, a0);
            pfrag(sacc[1][ks], srcA, srcB, odd, a1);
            #pragma unroll
            for (int nt = 0; nt < 8; nt++) {
                uint32_t b0 = Vs[(ks * 8 + t) * VS_STR + nt * 8 + g];
                uint32_t b1 = Vs[(ks * 8 + t + 4) * VS_STR + nt * 8 + g];
                mma8(o[0][nt], a0, b0, b1);
                mma8(o[1][nt], a1, b0, b1);
            }
        }

        __syncthreads();

        if (it + 2 < NIT) {
            uint32_t* Kn = sm4 + KS_OFF + buf * 64 * KS_STR;
            uint32_t* Vn = sm4 + VS_OFF + buf * 64 * VS_STR;
            const float* Kp = Kg + (size_t)(it + 2) * 64 * 64;
            const float* Vp = Vg + (size_t)(it + 2) * 64 * 64;
            #pragma unroll
            for (int j = 0; j < 8; j++) {
                int f = j * 128 + tid;
                int r = f >> 4, d4 = (f & 15) << 2;
                cp_async16(&Kn[r * KS_STR + d4], Kp + f * 4);
                cp_async16(&Vn[r * VS_STR + d4], Vp + f * 4);
            }
        }
        cp_commit();
    }

    // epilogue: normalize, round to tf32 (proj GEMM input), write [b, n, h*64+d]
    const int b = bh / NHEAD, hh = bh % NHEAD;
    #pragma unroll
    for (int mt = 0; mt < 2; mt++) {
        #pragma unroll
        for (int h = 0; h < 2; h++) {
            const float inv = 1.0f / lstate[mt][h];
            const int n = q0 + base + mt * 16 + g + 8 * h;
            float* orow = Out + ((size_t)(b * SEQ + n)) * CDIM + hh * 64;
            #pragma unroll
            for (int nt = 0; nt < 8; nt++) {
                float2 v = { tf32f(o[mt][nt][2 * h] * inv),
                             tf32f(o[mt][nt][2 * h + 1] * inv) };
                *reinterpret_cast<float2*>(orow + nt * 8 + 2 * t) = v;
            }
        }
    }
}

// ------------------------------- launcher -------------------------------------
extern "C" void kernel_launch(void* const* d_in, const int* in_sizes, int n_in,
                              void* d_out, int out_size)
{
    const float* x        = (const float*)d_in[0];
    const float* rope_cos = (const float*)d_in[1];
    const float* rope_sin = (const float*)d_in[2];
    const float* qkv_k    = (const float*)d_in[3];
    const float* qkv_b    = (const float*)d_in[4];
    const float* proj_k   = (const float*)d_in[5];
    const float* proj_b   = (const float*)d_in[6];
    const float* qw       = (const float*)d_in[7];
    const float* kw       = (const float*)d_in[8];
    float* out = (float*)d_out;

    float *p_qkv, *p_q, *p_k, *p_v, *p_attn, *p_xr, *p_wqr, *p_wpr;
    cudaGetSymbolAddress((void**)&p_qkv,  g_qkv);
    cudaGetSymbolAddress((void**)&p_q,    g_q);
    cudaGetSymbolAddress((void**)&p_k,    g_k);
    cudaGetSymbolAddress((void**)&p_v,    g_v);
    cudaGetSymbolAddress((void**)&p_attn, g_attn);
    cudaGetSymbolAddress((void**)&p_xr,   g_xr);
    cudaGetSymbolAddress((void**)&p_wqr,  g_wqr);
    cudaGetSymbolAddress((void**)&p_wpr,  g_wpr);

    cudaFuncSetAttribute(sgemm_tf32, cudaFuncAttributeMaxDynamicSharedMemorySize, SG_SMEM);
    cudaFuncSetAttribute(flash_tf32, cudaFuncAttributeMaxDynamicSharedMemorySize,
                         FLASH_SMEM_BYTES);

    // 0) pre-round inputs to tf32
    round_tf32<<<(MROWS * CDIM / 4 + 255) / 256, 256>>>(x, p_xr, MROWS * CDIM / 4);
    round_tf32<<<(CDIM * QKVN / 4 + 255) / 256, 256>>>(qkv_k, p_wqr, CDIM * QKVN / 4);
    round_tf32<<<(CDIM * CDIM / 4 + 255) / 256, 256>>>(proj_k, p_wpr, CDIM * CDIM / 4);

    // 1) QKV GEMM: [4096,768] x [768,2304]
    {
        dim3 grid(QKVN / 128, MROWS / 128);
        sgemm_tf32<<<grid, 256, SG_SMEM>>>(MROWS, QKVN, CDIM, p_xr, p_wqr, qkv_b, p_qkv);
    }

    // 2) RMSNorm + RoPE + scatter
    {
        int warps = BATCH * SEQ * NHEAD;
        int blocks = (warps * 32 + 255) / 256;
        qkv_post<<<blocks, 256>>>(p_qkv, rope_cos, rope_sin, qw, kw, p_q, p_k, p_v);
    }

    // 3) flash attention
    {
        dim3 grid(SEQ / BQ, BHTOT);
        flash_tf32<<<grid, 128, FLASH_SMEM_BYTES>>>(p_q, p_k, p_v, p_attn);
    }

    // 4) projection GEMM: [4096,768] x [768,768] -> d_out
    {
        dim3 grid(CDIM / 128, MROWS / 128);
        sgemm_tf32<<<grid, 256, SG_SMEM>>>(MROWS, CDIM, CDIM, p_attn, p_wpr, proj_b, out);
    }
}